// round 15
// baseline (speedup 1.0000x reference)
#include <cuda_runtime.h>
#include <cuda_bf16.h>

// ---------------------------------------------------------------------------
// MAGNN metapath-specific layer, GB300.
// Pipeline: frv table -> per-edge rotate/mean + logits (+segment max, counts)
//           -> scan -> bucket (CSR) -> exp/segment-sum -> per-node gather.
// ---------------------------------------------------------------------------

#define NMAX   100000
#define EMAX   250000
#define LMETA  4
#define HEADS  8
#define DIM    64
#define D2     32
#define ALPHA  0.01f

// ---- scratch (static __device__ arrays; no allocation allowed) ----
__device__ float        g_frv[LMETA * DIM];                    // 1 KB
__device__ float        g_hidden[(size_t)EMAX * DIM];          // 64 MB
__device__ float        g_logits[(size_t)EMAX * HEADS];        // 8 MB (logits -> aexp)
__device__ unsigned int g_amax[(size_t)NMAX * HEADS];          // 3.2 MB (monotone-mapped)
__device__ float        g_asum[(size_t)NMAX * HEADS];          // 3.2 MB
__device__ int          g_count[NMAX];
__device__ int          g_cursor[NMAX];
__device__ int          g_offset[NMAX + 1];
__device__ int          g_edge_of[EMAX];

// monotone map: float -> uint preserving order, so atomicMax(uint) == float max
__device__ __forceinline__ unsigned int fmap(float f) {
    unsigned int b = __float_as_uint(f);
    return (b & 0x80000000u) ? ~b : (b | 0x80000000u);
}
__device__ __forceinline__ float funmap(unsigned int u) {
    return (u & 0x80000000u) ? __uint_as_float(u & 0x7fffffffu)
                             : __uint_as_float(~u);
}

// ---------------------------------------------------------------------------
// K0: zero the per-node accumulators
// ---------------------------------------------------------------------------
__global__ void k_zero(int N) {
    int stride = gridDim.x * blockDim.x;
    int tid = blockIdx.x * blockDim.x + threadIdx.x;
    for (int i = tid; i < N * HEADS; i += stride) {
        g_amax[i] = 0u;       // maps below every real float value
        g_asum[i] = 0.0f;
    }
    for (int i = tid; i < N; i += stride) {
        g_count[i]  = 0;
        g_cursor[i] = 0;
    }
}

// ---------------------------------------------------------------------------
// K_frv: build the 4x32 complex rotation table.
// ETYPES = {0,2,1}; rv2[e]: 0->rv0, 1->conj(rv0), 2->rv1, 3->conj(rv1)
// fr[3]=identity; fr[i] = fr[i+1] * rv2[ETYPES[i]]
// ---------------------------------------------------------------------------
__global__ void k_frv(const float* __restrict__ r_vec) {
    int d = threadIdx.x;            // 0..31
    if (d >= D2) return;
    float2 rv[2];
    #pragma unroll
    for (int r = 0; r < 2; r++) {
        float re = r_vec[r * DIM + 2 * d];
        float im = r_vec[r * DIM + 2 * d + 1];
        float inv = rsqrtf(re * re + im * im);
        rv[r] = make_float2(re * inv, im * inv);
    }
    const int etypes[3] = {0, 2, 1};
    float fre = 1.0f, fim = 0.0f;
    g_frv[3 * DIM + 2 * d]     = 1.0f;
    g_frv[3 * DIM + 2 * d + 1] = 0.0f;
    #pragma unroll
    for (int i = 2; i >= 0; i--) {
        int et = etypes[i];
        float2 base = rv[et >> 1];
        float rre = base.x;
        float rim = (et & 1) ? -base.y : base.y;
        float nre = fre * rre - fim * rim;
        float nim = fre * rim + fim * rre;
        fre = nre; fim = nim;
        g_frv[i * DIM + 2 * d]     = fre;
        g_frv[i * DIM + 2 * d + 1] = fim;
    }
}

// ---------------------------------------------------------------------------
// K1: one warp per edge.
//   - gather 4 feature rows, complex-rotate by frv, mean -> hidden[e]
//   - logits[e,h] = leakyrelu( center . attn1_w[h]  +  hidden . attn2[h] )
//   - atomicMax segment max, atomic count for CSR
// ---------------------------------------------------------------------------
__global__ void k_edge(const float* __restrict__ features,
                       const int*   __restrict__ idx,
                       const int*   __restrict__ edge_dst,
                       const float* __restrict__ attn1_w,
                       const float* __restrict__ attn2,
                       int E) {
    __shared__ float s_w1[HEADS * DIM];
    __shared__ float s_w2[HEADS * DIM];
    __shared__ float s_frv[LMETA * DIM];
    for (int i = threadIdx.x; i < HEADS * DIM; i += blockDim.x) {
        s_w1[i] = attn1_w[i];
        s_w2[i] = attn2[i];
    }
    for (int i = threadIdx.x; i < LMETA * DIM; i += blockDim.x)
        s_frv[i] = g_frv[i];
    __syncthreads();

    int warp = threadIdx.x >> 5;
    int lane = threadIdx.x & 31;
    int e = blockIdx.x * (blockDim.x >> 5) + warp;
    if (e >= E) return;

    const int* ip = idx + (size_t)e * LMETA;
    float sr = 0.0f, si = 0.0f;
    float cr = 0.0f, ci = 0.0f;
    #pragma unroll
    for (int l = 0; l < LMETA; l++) {
        int node = __ldg(ip + l);
        float2 x = *reinterpret_cast<const float2*>(features + (size_t)node * DIM + 2 * lane);
        if (l == LMETA - 1) { cr = x.x; ci = x.y; }
        float fr_ = s_frv[l * DIM + 2 * lane];
        float fi_ = s_frv[l * DIM + 2 * lane + 1];
        sr += x.x * fr_ - x.y * fi_;
        si += x.x * fi_ + x.y * fr_;
    }
    float hr = sr * 0.25f, hi = si * 0.25f;
    *reinterpret_cast<float2*>(g_hidden + (size_t)e * DIM + 2 * lane) = make_float2(hr, hi);

    float aval = 0.0f;
    #pragma unroll
    for (int h = 0; h < HEADS; h++) {
        float p = cr * s_w1[h * DIM + 2 * lane] + ci * s_w1[h * DIM + 2 * lane + 1]
                + hr * s_w2[h * DIM + 2 * lane] + hi * s_w2[h * DIM + 2 * lane + 1];
        #pragma unroll
        for (int off = 16; off > 0; off >>= 1)
            p += __shfl_xor_sync(0xffffffffu, p, off);
        if (lane == h) aval = p;
    }
    int dst = __ldg(edge_dst + e);
    if (lane < HEADS) {
        float a = aval > 0.0f ? aval : ALPHA * aval;
        g_logits[(size_t)e * HEADS + lane] = a;
        atomicMax(&g_amax[(size_t)dst * HEADS + lane], fmap(a));
    }
    if (lane == 0) atomicAdd(&g_count[dst], 1);
}

// ---------------------------------------------------------------------------
// K_scan: single block, 1024 threads, 4x coarsened Hillis-Steele exclusive scan
// of g_count -> g_offset (plus g_offset[N] = total).
// ---------------------------------------------------------------------------
__global__ void k_scan(int n) {
    __shared__ int sh[1024];
    const int T = 1024;
    int running = 0;
    for (int base = 0; base < n; base += T * 4) {
        int v[4];
        int local = 0;
        int i0 = base + threadIdx.x * 4;
        #pragma unroll
        for (int k = 0; k < 4; k++) {
            int i = i0 + k;
            v[k] = (i < n) ? g_count[i] : 0;
            local += v[k];
        }
        sh[threadIdx.x] = local;
        __syncthreads();
        for (int off = 1; off < T; off <<= 1) {
            int t = (threadIdx.x >= (unsigned)off) ? sh[threadIdx.x - off] : 0;
            __syncthreads();
            sh[threadIdx.x] += t;
            __syncthreads();
        }
        int excl = running + sh[threadIdx.x] - local;
        #pragma unroll
        for (int k = 0; k < 4; k++) {
            int i = i0 + k;
            if (i < n) g_offset[i] = excl;
            excl += v[k];
        }
        running += sh[T - 1];
        __syncthreads();
    }
    if (threadIdx.x == 0) g_offset[n] = running;
}

// ---------------------------------------------------------------------------
// K_bucket: scatter edge ids into CSR order.
// ---------------------------------------------------------------------------
__global__ void k_bucket(const int* __restrict__ edge_dst, int E) {
    int e = blockIdx.x * blockDim.x + threadIdx.x;
    if (e >= E) return;
    int dst = edge_dst[e];
    int pos = atomicAdd(&g_cursor[dst], 1);
    g_edge_of[g_offset[dst] + pos] = e;
}

// ---------------------------------------------------------------------------
// K_exp: aexp = exp(a - amax[dst]); accumulate asum. One thread per (e, h).
// ---------------------------------------------------------------------------
__global__ void k_exp(const int* __restrict__ edge_dst, int E) {
    int tid = blockIdx.x * blockDim.x + threadIdx.x;
    int total = E * HEADS;
    if (tid >= total) return;
    int e = tid >> 3;
    int h = tid & 7;
    int dst = __ldg(edge_dst + e);
    float amax = funmap(g_amax[(size_t)dst * HEADS + h]);
    float v = expf(g_logits[tid] - amax);
    g_logits[tid] = v;
    atomicAdd(&g_asum[(size_t)dst * HEADS + h], v);
}

// ---------------------------------------------------------------------------
// K_out: one warp per node. Accumulate aexp-weighted hidden in registers,
// divide by asum once, single coalesced 2KB write per node.
// ---------------------------------------------------------------------------
__global__ void k_out(float* __restrict__ out, int N) {
    int warp = threadIdx.x >> 5;
    int lane = threadIdx.x & 31;
    int n = blockIdx.x * (blockDim.x >> 5) + warp;
    if (n >= N) return;

    int beg = g_offset[n];
    int end = g_offset[n + 1];

    float acc0[HEADS];
    float acc1[HEADS];
    #pragma unroll
    for (int h = 0; h < HEADS; h++) { acc0[h] = 0.0f; acc1[h] = 0.0f; }

    for (int j = beg; j < end; j++) {
        int e = g_edge_of[j];
        float2 hd = *reinterpret_cast<const float2*>(g_hidden + (size_t)e * DIM + 2 * lane);
        float my = (lane < HEADS) ? g_logits[(size_t)e * HEADS + lane] : 0.0f;
        #pragma unroll
        for (int h = 0; h < HEADS; h++) {
            float ae = __shfl_sync(0xffffffffu, my, h);
            acc0[h] += ae * hd.x;
            acc1[h] += ae * hd.y;
        }
    }

    float s = (lane < HEADS) ? g_asum[(size_t)n * HEADS + lane] : 0.0f;
    float* obase = out + (size_t)n * HEADS * DIM;
    #pragma unroll
    for (int h = 0; h < HEADS; h++) {
        float sh_ = __shfl_sync(0xffffffffu, s, h);
        float iv = (sh_ > 0.0f) ? (1.0f / sh_) : 0.0f;
        *reinterpret_cast<float2*>(obase + h * DIM + 2 * lane) =
            make_float2(acc0[h] * iv, acc1[h] * iv);
    }
}

// ---------------------------------------------------------------------------
// launch
// ---------------------------------------------------------------------------
extern "C" void kernel_launch(void* const* d_in, const int* in_sizes, int n_in,
                              void* d_out, int out_size) {
    const float* features = (const float*)d_in[0];   // (N, 64)
    const float* r_vec    = (const float*)d_in[1];   // (2, 32, 2)
    const float* attn1_w  = (const float*)d_in[2];   // (8, 64)
    const float* attn2    = (const float*)d_in[3];   // (1, 8, 64)
    const int*   idx      = (const int*)d_in[4];     // (E, 4)
    const int*   edge_dst = (const int*)d_in[5];     // (E,)
    float*       out      = (float*)d_out;           // (N, 8, 64)

    int N = in_sizes[0] / DIM;
    int E = in_sizes[5];

    // K0: zero accumulators
    {
        int threads = 256;
        int blocks = (N * HEADS + threads - 1) / threads;
        if (blocks > 2048) blocks = 2048;
        k_zero<<<blocks, threads>>>(N);
    }
    // frv table
    k_frv<<<1, 32>>>(r_vec);
    // per-edge rotate/mean + logits + segment-max + counts
    {
        int threads = 256;                       // 8 warps = 8 edges / block
        int blocks = (E + 7) / 8;
        k_edge<<<blocks, threads>>>(features, idx, edge_dst, attn1_w, attn2, E);
    }
    // exclusive scan of counts
    k_scan<<<1, 1024>>>(N);
    // CSR bucketing
    {
        int threads = 256;
        int blocks = (E + threads - 1) / threads;
        k_bucket<<<blocks, threads>>>(edge_dst, E);
    }
    // exp + segment sum
    {
        int threads = 256;
        int total = E * HEADS;
        int blocks = (total + threads - 1) / threads;
        k_exp<<<blocks, threads>>>(edge_dst, E);
    }
    // per-node weighted gather -> output
    {
        int threads = 256;                       // 8 warps = 8 nodes / block
        int blocks = (N + 7) / 8;
        k_out<<<blocks, threads>>>(out, N);
    }
}

// round 16
// speedup vs baseline: 1.0055x; 1.0055x over previous
#include <cuda_runtime.h>
#include <cuda_bf16.h>

// ---------------------------------------------------------------------------
// MAGNN metapath-specific layer, GB300.
// Pipeline: frv table -> per-edge rotate/mean + logits (+segment max, counts)
//           -> scan -> bucket (CSR) -> exp/segment-sum -> per-node gather.
// ---------------------------------------------------------------------------

#define NMAX   100000
#define EMAX   250000
#define LMETA  4
#define HEADS  8
#define DIM    64
#define D2     32
#define ALPHA  0.01f

// ---- scratch (static __device__ arrays; no allocation allowed) ----
__device__ float        g_frv[LMETA * DIM];                    // 1 KB
__device__ float        g_hidden[(size_t)EMAX * DIM];          // 64 MB
__device__ float        g_logits[(size_t)EMAX * HEADS];        // 8 MB (logits -> aexp)
__device__ unsigned int g_amax[(size_t)NMAX * HEADS];          // 3.2 MB (monotone-mapped)
__device__ float        g_asum[(size_t)NMAX * HEADS];          // 3.2 MB
__device__ int          g_count[NMAX];
__device__ int          g_cursor[NMAX];
__device__ int          g_offset[NMAX + 1];
__device__ int          g_edge_of[EMAX];

// monotone map: float -> uint preserving order, so atomicMax(uint) == float max
__device__ __forceinline__ unsigned int fmap(float f) {
    unsigned int b = __float_as_uint(f);
    return (b & 0x80000000u) ? ~b : (b | 0x80000000u);
}
__device__ __forceinline__ float funmap(unsigned int u) {
    return (u & 0x80000000u) ? __uint_as_float(u & 0x7fffffffu)
                             : __uint_as_float(~u);
}

// ---------------------------------------------------------------------------
// K0: zero the per-node accumulators
// ---------------------------------------------------------------------------
__global__ void k_zero(int N) {
    int stride = gridDim.x * blockDim.x;
    int tid = blockIdx.x * blockDim.x + threadIdx.x;
    for (int i = tid; i < N * HEADS; i += stride) {
        g_amax[i] = 0u;       // maps below every real float value
        g_asum[i] = 0.0f;
    }
    for (int i = tid; i < N; i += stride) {
        g_count[i]  = 0;
        g_cursor[i] = 0;
    }
}

// ---------------------------------------------------------------------------
// K_frv: build the 4x32 complex rotation table.
// ETYPES = {0,2,1}; rv2[e]: 0->rv0, 1->conj(rv0), 2->rv1, 3->conj(rv1)
// fr[3]=identity; fr[i] = fr[i+1] * rv2[ETYPES[i]]
// ---------------------------------------------------------------------------
__global__ void k_frv(const float* __restrict__ r_vec) {
    int d = threadIdx.x;            // 0..31
    if (d >= D2) return;
    float2 rv[2];
    #pragma unroll
    for (int r = 0; r < 2; r++) {
        float re = r_vec[r * DIM + 2 * d];
        float im = r_vec[r * DIM + 2 * d + 1];
        float inv = rsqrtf(re * re + im * im);
        rv[r] = make_float2(re * inv, im * inv);
    }
    const int etypes[3] = {0, 2, 1};
    float fre = 1.0f, fim = 0.0f;
    g_frv[3 * DIM + 2 * d]     = 1.0f;
    g_frv[3 * DIM + 2 * d + 1] = 0.0f;
    #pragma unroll
    for (int i = 2; i >= 0; i--) {
        int et = etypes[i];
        float2 base = rv[et >> 1];
        float rre = base.x;
        float rim = (et & 1) ? -base.y : base.y;
        float nre = fre * rre - fim * rim;
        float nim = fre * rim + fim * rre;
        fre = nre; fim = nim;
        g_frv[i * DIM + 2 * d]     = fre;
        g_frv[i * DIM + 2 * d + 1] = fim;
    }
}

// ---------------------------------------------------------------------------
// K1: one warp per edge.
//   - gather 4 feature rows, complex-rotate by frv, mean -> hidden[e]
//   - logits[e,h] = leakyrelu( center . attn1_w[h]  +  hidden . attn2[h] )
//   - atomicMax segment max, atomic count for CSR
// ---------------------------------------------------------------------------
__global__ void k_edge(const float* __restrict__ features,
                       const int*   __restrict__ idx,
                       const int*   __restrict__ edge_dst,
                       const float* __restrict__ attn1_w,
                       const float* __restrict__ attn2,
                       int E) {
    __shared__ float s_w1[HEADS * DIM];
    __shared__ float s_w2[HEADS * DIM];
    __shared__ float s_frv[LMETA * DIM];
    for (int i = threadIdx.x; i < HEADS * DIM; i += blockDim.x) {
        s_w1[i] = attn1_w[i];
        s_w2[i] = attn2[i];
    }
    for (int i = threadIdx.x; i < LMETA * DIM; i += blockDim.x)
        s_frv[i] = g_frv[i];
    __syncthreads();

    int warp = threadIdx.x >> 5;
    int lane = threadIdx.x & 31;
    int e = blockIdx.x * (blockDim.x >> 5) + warp;
    if (e >= E) return;

    const int* ip = idx + (size_t)e * LMETA;
    float sr = 0.0f, si = 0.0f;
    float cr = 0.0f, ci = 0.0f;
    #pragma unroll
    for (int l = 0; l < LMETA; l++) {
        int node = __ldg(ip + l);
        float2 x = *reinterpret_cast<const float2*>(features + (size_t)node * DIM + 2 * lane);
        if (l == LMETA - 1) { cr = x.x; ci = x.y; }
        float fr_ = s_frv[l * DIM + 2 * lane];
        float fi_ = s_frv[l * DIM + 2 * lane + 1];
        sr += x.x * fr_ - x.y * fi_;
        si += x.x * fi_ + x.y * fr_;
    }
    float hr = sr * 0.25f, hi = si * 0.25f;
    *reinterpret_cast<float2*>(g_hidden + (size_t)e * DIM + 2 * lane) = make_float2(hr, hi);

    float aval = 0.0f;
    #pragma unroll
    for (int h = 0; h < HEADS; h++) {
        float p = cr * s_w1[h * DIM + 2 * lane] + ci * s_w1[h * DIM + 2 * lane + 1]
                + hr * s_w2[h * DIM + 2 * lane] + hi * s_w2[h * DIM + 2 * lane + 1];
        #pragma unroll
        for (int off = 16; off > 0; off >>= 1)
            p += __shfl_xor_sync(0xffffffffu, p, off);
        if (lane == h) aval = p;
    }
    int dst = __ldg(edge_dst + e);
    if (lane < HEADS) {
        float a = aval > 0.0f ? aval : ALPHA * aval;
        g_logits[(size_t)e * HEADS + lane] = a;
        atomicMax(&g_amax[(size_t)dst * HEADS + lane], fmap(a));
    }
    if (lane == 0) atomicAdd(&g_count[dst], 1);
}

// ---------------------------------------------------------------------------
// K_scan: single block, 1024 threads, 4x coarsened Hillis-Steele exclusive scan
// of g_count -> g_offset (plus g_offset[N] = total).
// ---------------------------------------------------------------------------
__global__ void k_scan(int n) {
    __shared__ int sh[1024];
    const int T = 1024;
    int running = 0;
    for (int base = 0; base < n; base += T * 4) {
        int v[4];
        int local = 0;
        int i0 = base + threadIdx.x * 4;
        #pragma unroll
        for (int k = 0; k < 4; k++) {
            int i = i0 + k;
            v[k] = (i < n) ? g_count[i] : 0;
            local += v[k];
        }
        sh[threadIdx.x] = local;
        __syncthreads();
        for (int off = 1; off < T; off <<= 1) {
            int t = (threadIdx.x >= (unsigned)off) ? sh[threadIdx.x - off] : 0;
            __syncthreads();
            sh[threadIdx.x] += t;
            __syncthreads();
        }
        int excl = running + sh[threadIdx.x] - local;
        #pragma unroll
        for (int k = 0; k < 4; k++) {
            int i = i0 + k;
            if (i < n) g_offset[i] = excl;
            excl += v[k];
        }
        running += sh[T - 1];
        __syncthreads();
    }
    if (threadIdx.x == 0) g_offset[n] = running;
}

// ---------------------------------------------------------------------------
// K_bucket: scatter edge ids into CSR order.
// ---------------------------------------------------------------------------
__global__ void k_bucket(const int* __restrict__ edge_dst, int E) {
    int e = blockIdx.x * blockDim.x + threadIdx.x;
    if (e >= E) return;
    int dst = edge_dst[e];
    int pos = atomicAdd(&g_cursor[dst], 1);
    g_edge_of[g_offset[dst] + pos] = e;
}

// ---------------------------------------------------------------------------
// K_exp: aexp = exp(a - amax[dst]); accumulate asum. One thread per (e, h).
// ---------------------------------------------------------------------------
__global__ void k_exp(const int* __restrict__ edge_dst, int E) {
    int tid = blockIdx.x * blockDim.x + threadIdx.x;
    int total = E * HEADS;
    if (tid >= total) return;
    int e = tid >> 3;
    int h = tid & 7;
    int dst = __ldg(edge_dst + e);
    float amax = funmap(g_amax[(size_t)dst * HEADS + h]);
    float v = expf(g_logits[tid] - amax);
    g_logits[tid] = v;
    atomicAdd(&g_asum[(size_t)dst * HEADS + h], v);
}

// ---------------------------------------------------------------------------
// K_out: one warp per node. Accumulate aexp-weighted hidden in registers,
// divide by asum once, single coalesced 2KB write per node.
// ---------------------------------------------------------------------------
__global__ void k_out(float* __restrict__ out, int N) {
    int warp = threadIdx.x >> 5;
    int lane = threadIdx.x & 31;
    int n = blockIdx.x * (blockDim.x >> 5) + warp;
    if (n >= N) return;

    int beg = g_offset[n];
    int end = g_offset[n + 1];

    float acc0[HEADS];
    float acc1[HEADS];
    #pragma unroll
    for (int h = 0; h < HEADS; h++) { acc0[h] = 0.0f; acc1[h] = 0.0f; }

    for (int j = beg; j < end; j++) {
        int e = g_edge_of[j];
        float2 hd = *reinterpret_cast<const float2*>(g_hidden + (size_t)e * DIM + 2 * lane);
        float my = (lane < HEADS) ? g_logits[(size_t)e * HEADS + lane] : 0.0f;
        #pragma unroll
        for (int h = 0; h < HEADS; h++) {
            float ae = __shfl_sync(0xffffffffu, my, h);
            acc0[h] += ae * hd.x;
            acc1[h] += ae * hd.y;
        }
    }

    float s = (lane < HEADS) ? g_asum[(size_t)n * HEADS + lane] : 0.0f;
    float* obase = out + (size_t)n * HEADS * DIM;
    #pragma unroll
    for (int h = 0; h < HEADS; h++) {
        float sh_ = __shfl_sync(0xffffffffu, s, h);
        float iv = (sh_ > 0.0f) ? (1.0f / sh_) : 0.0f;
        *reinterpret_cast<float2*>(obase + h * DIM + 2 * lane) =
            make_float2(acc0[h] * iv, acc1[h] * iv);
    }
}

// ---------------------------------------------------------------------------
// launch
// ---------------------------------------------------------------------------
extern "C" void kernel_launch(void* const* d_in, const int* in_sizes, int n_in,
                              void* d_out, int out_size) {
    const float* features = (const float*)d_in[0];   // (N, 64)
    const float* r_vec    = (const float*)d_in[1];   // (2, 32, 2)
    const float* attn1_w  = (const float*)d_in[2];   // (8, 64)
    const float* attn2    = (const float*)d_in[3];   // (1, 8, 64)
    const int*   idx      = (const int*)d_in[4];     // (E, 4)
    const int*   edge_dst = (const int*)d_in[5];     // (E,)
    float*       out      = (float*)d_out;           // (N, 8, 64)

    int N = in_sizes[0] / DIM;
    int E = in_sizes[5];

    // K0: zero accumulators
    {
        int threads = 256;
        int blocks = (N * HEADS + threads - 1) / threads;
        if (blocks > 2048) blocks = 2048;
        k_zero<<<blocks, threads>>>(N);
    }
    // frv table
    k_frv<<<1, 32>>>(r_vec);
    // per-edge rotate/mean + logits + segment-max + counts
    {
        int threads = 256;                       // 8 warps = 8 edges / block
        int blocks = (E + 7) / 8;
        k_edge<<<blocks, threads>>>(features, idx, edge_dst, attn1_w, attn2, E);
    }
    // exclusive scan of counts
    k_scan<<<1, 1024>>>(N);
    // CSR bucketing
    {
        int threads = 256;
        int blocks = (E + threads - 1) / threads;
        k_bucket<<<blocks, threads>>>(edge_dst, E);
    }
    // exp + segment sum
    {
        int threads = 256;
        int total = E * HEADS;
        int blocks = (total + threads - 1) / threads;
        k_exp<<<blocks, threads>>>(edge_dst, E);
    }
    // per-node weighted gather -> output
    {
        int threads = 256;                       // 8 warps = 8 nodes / block
        int blocks = (N + 7) / 8;
        k_out<<<blocks, threads>>>(out, N);
    }
}